// round 16
// baseline (speedup 1.0000x reference)
#include <cuda_runtime.h>
#include <cuda_fp16.h>
#include <cstdint>
#include <math.h>

// LSTM cell: fp16 mma.sync GEMM + register-direct fused gate epilogue.
// Round 16: round-15 + per-thread pointer-increment loaders (no per-stage
// address IMADs) + early cell prefetch into registers before the final stages.

#define BATCH 4096
#define UNITS 1024
#define KDIM  2048

#define BM 128
#define BNU 32              // units per CTA (x4 gates = 128 gemm cols)
#define BK 64
#define NSTAGE (KDIM / BK)  // 32
#define NBUF 3

#define ROW_B   144                     // 128B data + 16B pad (conflict-free)
#define TILE_B  (128 * ROW_B)           // 18432
#define OFF_AH  0
#define OFF_BH  TILE_B
#define STAGE_B (2 * TILE_B)            // 36864
#define MBAR_B  128
#define SMEM_TOTAL (MBAR_B + NBUF * STAGE_B)   // 110720 (x2 CTAs <= 228KB)

// ---------------- device scratch ----------------
__device__ __half g_Ah[(size_t)BATCH * KDIM];
__device__ __half g_Bh[(size_t)4 * UNITS * KDIM];   // row = gate*1024 + n, k contiguous

// ---------------- helpers ----------------
__device__ __forceinline__ uint32_t smem_u32(const void* p) {
    uint32_t a;
    asm("{ .reg .u64 t; cvta.to.shared.u64 t, %1; cvt.u32.u64 %0, t; }" : "=r"(a) : "l"(p));
    return a;
}
__device__ __forceinline__ void cp16(uint32_t dst, const void* src) {
    asm volatile("cp.async.cg.shared.global [%0], [%1], 16;" :: "r"(dst), "l"(src));
}
__device__ __forceinline__ void cpasync_arrive(uint32_t mbar) {
    asm volatile("cp.async.mbarrier.arrive.noinc.shared.b64 [%0];" :: "r"(mbar) : "memory");
}
__device__ __forceinline__ void mbar_init(uint32_t mbar, uint32_t cnt) {
    asm volatile("mbarrier.init.shared.b64 [%0], %1;" :: "r"(mbar), "r"(cnt) : "memory");
}
__device__ __forceinline__ void mbar_arrive(uint32_t mbar) {
    asm volatile("mbarrier.arrive.shared.b64 _, [%0];" :: "r"(mbar) : "memory");
}
__device__ __forceinline__ void mbar_wait(uint32_t mbar, uint32_t parity) {
    uint32_t done;
    asm volatile(
        "{\n\t.reg .pred p;\n\t"
        "mbarrier.try_wait.parity.acquire.cta.shared::cta.b64 p, [%1], %2;\n\t"
        "selp.b32 %0, 1, 0, p;\n\t}"
        : "=r"(done) : "r"(mbar), "r"(parity) : "memory");
    while (!done) {
        asm volatile(
            "{\n\t.reg .pred p;\n\t"
            "mbarrier.try_wait.parity.acquire.cta.shared::cta.b64 p, [%1], %2, 0x989680;\n\t"
            "selp.b32 %0, 1, 0, p;\n\t}"
            : "=r"(done) : "r"(mbar), "r"(parity) : "memory");
    }
}

#define LDSM4(r0, r1, r2, r3, addr) \
    asm volatile("ldmatrix.sync.aligned.m8n8.x4.shared.b16 {%0,%1,%2,%3}, [%4];" \
        : "=r"(r0), "=r"(r1), "=r"(r2), "=r"(r3) : "r"(addr))

__device__ __forceinline__ void mma_f16(float* c, const uint32_t* a, const uint32_t* b) {
    asm volatile(
        "mma.sync.aligned.m16n8k16.row.col.f32.f16.f16.f32 "
        "{%0,%1,%2,%3}, {%4,%5,%6,%7}, {%8,%9}, {%0,%1,%2,%3};"
        : "+f"(c[0]), "+f"(c[1]), "+f"(c[2]), "+f"(c[3])
        : "r"(a[0]), "r"(a[1]), "r"(a[2]), "r"(a[3]), "r"(b[0]), "r"(b[1]));
}

__device__ __forceinline__ float sig_(float x) {
    x = fminf(fmaxf(x, -30.f), 30.f);
    return __fdividef(1.f, 1.f + __expf(-x));
}
__device__ __forceinline__ float tanh_(float x) {
    x = fminf(fmaxf(x, -15.f), 15.f);
    float e = __expf(2.f * x);
    return __fdividef(e - 1.f, e + 1.f);
}

// ---------------- merged precompute ----------------
__global__ __launch_bounds__(256) void prep_kernel(
    const float* __restrict__ hid, const float* __restrict__ inp,
    const float* __restrict__ Wf, const float* __restrict__ Wi,
    const float* __restrict__ Wc, const float* __restrict__ Wo)
{
    __shared__ float tile[64][33];
    const int bid = blockIdx.x;
    if (bid < 4096) {
        const int row = bid;
        const int c8  = threadIdx.x * 8;   // 0..2040
        const float* src = (c8 < 1024) ? &hid[(size_t)row * 1024 + c8]
                                       : &inp[(size_t)row * 1024 + (c8 - 1024)];
        const float4 v0 = *(const float4*)src;
        const float4 v1 = *(const float4*)(src + 4);
        __half h[8];
        h[0] = __float2half_rn(v0.x); h[1] = __float2half_rn(v0.y);
        h[2] = __float2half_rn(v0.z); h[3] = __float2half_rn(v0.w);
        h[4] = __float2half_rn(v1.x); h[5] = __float2half_rn(v1.y);
        h[6] = __float2half_rn(v1.z); h[7] = __float2half_rn(v1.w);
        *(uint4*)&g_Ah[(size_t)row * KDIM + c8] = *(uint4*)h;
    } else {
        const int t  = bid - 4096;          // 4096 blocks: gate(4) x ktile(32) x ntile(32)
        const int g  = t >> 10;
        const int k0 = ((t >> 5) & 31) * 64;
        const int n0 = (t & 31) * 32;
        const float* W = (g == 0) ? Wf : (g == 1) ? Wi : (g == 2) ? Wc : Wo;
        const int lr = threadIdx.x >> 2;          // 0..63 (k row)
        const int lc = (threadIdx.x & 3) * 8;     // 0,8,16,24 (n col base)
        const float* src = &W[(size_t)(k0 + lr) * UNITS + n0 + lc];
        const float4 v0 = *(const float4*)src;
        const float4 v1 = *(const float4*)(src + 4);
        tile[lr][lc + 0] = v0.x; tile[lr][lc + 1] = v0.y;
        tile[lr][lc + 2] = v0.z; tile[lr][lc + 3] = v0.w;
        tile[lr][lc + 4] = v1.x; tile[lr][lc + 5] = v1.y;
        tile[lr][lc + 6] = v1.z; tile[lr][lc + 7] = v1.w;
        __syncthreads();
        const int n  = threadIdx.x >> 3;          // 0..31
        const int kq = (threadIdx.x & 7) * 8;     // 0..56
        __half h[8];
        #pragma unroll
        for (int j = 0; j < 8; j++)
            h[j] = __float2half_rn(tile[kq + j][n]);
        size_t o = ((size_t)g * UNITS + n0 + n) * KDIM + k0 + kq;
        *(uint4*)&g_Bh[o] = *(uint4*)h;
    }
}

// ---------------- fused GEMM + register epilogue ----------------
__global__ __launch_bounds__(256, 2) void gemm_kernel(
    const float* __restrict__ cell,
    const float* __restrict__ bfp, const float* __restrict__ bip,
    const float* __restrict__ bcp, const float* __restrict__ bop,
    float* __restrict__ out_h, float* __restrict__ out_c)
{
    extern __shared__ char smem[];
    const uint32_t sb = smem_u32(smem);
    const int tid  = threadIdx.x;
    const int wid  = tid >> 5;
    const int lane = tid & 31;
    const int warp_m = wid & 1;    // 64 rows
    const int warp_n = wid >> 1;   // 0..3 -> 8 units each, all 4 gates
    const int m0 = blockIdx.y * BM;
    const int n0 = blockIdx.x * BNU;

    if (tid == 0) {
        mbar_init(sb + 0,  256);
        mbar_init(sb + 8,  256);
        mbar_init(sb + 16, 256);
        mbar_init(sb + 24, 8);
        mbar_init(sb + 32, 8);
        mbar_init(sb + 40, 8);
    }
    __syncthreads();

    const uint32_t buf0 = sb + MBAR_B;

    // ---- pointer-increment loader state (advance 2*BK bytes per stage)
    const int row = tid >> 3;            // 0..31 for i-group base; rows row+32i
    const int c   = tid & 7;
    // per-thread smem offsets (constant across stages)
    uint32_t s_a[4], s_b[4];
    const __half* g_a[4];
    const __half* g_b[4];
    #pragma unroll
    for (int i = 0; i < 4; i++) {
        const int r = row + i * 32;
        s_a[i] = OFF_AH + r * ROW_B + c * 16;
        s_b[i] = OFF_BH + r * ROW_B + c * 16;
        g_a[i] = &g_Ah[(size_t)(m0 + r) * KDIM + c * 8];
        const size_t gr = (size_t)(r >> 5) * UNITS + n0 + (r & 31);
        g_b[i] = &g_Bh[gr * KDIM + c * 8];
    }

    auto issue_stage = [&](int s, int b) {
        const uint32_t base = buf0 + b * STAGE_B;
        const int koff = s * BK;
        #pragma unroll
        for (int i = 0; i < 4; i++) {
            cp16(base + s_a[i], g_a[i] + koff);
            cp16(base + s_b[i], g_b[i] + koff);
        }
        cpasync_arrive(sb + b * 8);
    };

    const uint32_t a_off = (uint32_t)((warp_m * 64 + (lane & 15)) * ROW_B + (lane >> 4) * 16);
    const uint32_t b_off = (uint32_t)((((lane >> 4) & 1) * 32 + warp_n * 8 + (lane & 7)) * ROW_B
                                      + ((lane >> 3) & 1) * 16);

    float acc[4][4][4];   // [mt rows][gate][q]
    #pragma unroll
    for (int i = 0; i < 4; i++)
        #pragma unroll
        for (int j = 0; j < 4; j++)
            #pragma unroll
            for (int q = 0; q < 4; q++) acc[i][j][q] = 0.f;

    // epilogue coordinates (needed early for cell prefetch)
    const int fr = lane >> 2;
    const int fc = (lane & 3) * 2;
    const int ucol = n0 + warp_n * 8 + fc;
    float2 cellv[4][2];
    bool cell_loaded = false;

    auto stage_body = [&](int s, int b, int prodPar, int consPar,
                          bool produce, bool freewait) {
        const int b2 = (b + 2) % 3;
        if (produce) {
            if (freewait) mbar_wait(sb + 24 + b2 * 8, prodPar);
            issue_stage(s + 2, b2);
        } else if (!cell_loaded) {
            // final stages: prefetch cell tile into registers (latency overlaps
            // the last two stages' MMAs)
            #pragma unroll
            for (int mt = 0; mt < 4; mt++)
                #pragma unroll
                for (int q = 0; q < 2; q++) {
                    const int r = m0 + warp_m * 64 + mt * 16 + fr + q * 8;
                    cellv[mt][q] = *(const float2*)&cell[(size_t)r * UNITS + ucol];
                }
            cell_loaded = true;
        }
        mbar_wait(sb + b * 8, consPar);

        const uint32_t base = buf0 + b * STAGE_B;
        #pragma unroll
        for (int ksub = 0; ksub < 4; ksub++) {
            const uint32_t kb = ksub * 32;
            uint32_t aH[4][4], bH[4][2];
            #pragma unroll
            for (int mt = 0; mt < 4; mt++) {
                const uint32_t ra = base + a_off + mt * 16 * ROW_B + kb;
                LDSM4(aH[mt][0], aH[mt][1], aH[mt][2], aH[mt][3], ra + OFF_AH);
            }
            #pragma unroll
            for (int p = 0; p < 2; p++) {
                const uint32_t rb = base + b_off + p * 64 * ROW_B + kb;
                LDSM4(bH[2*p][0], bH[2*p][1], bH[2*p+1][0], bH[2*p+1][1], rb + OFF_BH);
            }
            if (ksub == 3) {
                if (lane == 0) mbar_arrive(sb + 24 + b * 8);
            }
            #pragma unroll
            for (int mt = 0; mt < 4; mt++)
                #pragma unroll
                for (int g = 0; g < 4; g++)
                    mma_f16(acc[mt][g], aH[mt], bH[g]);
        }
    };

    issue_stage(0, 0);
    issue_stage(1, 1);

    #pragma unroll 1
    for (int i = 0; i < 10; i++) {
        const int s = i * 3;
        const int p = i & 1;
        stage_body(s,     0, p ^ 1, p, true, i >= 1);
        stage_body(s + 1, 1, p,     p, true, true);
        stage_body(s + 2, 2, p,     p, true, true);
    }
    stage_body(30, 0, 0, 0, false, false);
    stage_body(31, 1, 0, 0, false, false);

    // ---- register-direct epilogue
    const float2 Bf = *(const float2*)&bfp[ucol];
    const float2 Bi = *(const float2*)&bip[ucol];
    const float2 Bc = *(const float2*)&bcp[ucol];
    const float2 Bo = *(const float2*)&bop[ucol];

    #pragma unroll
    for (int mt = 0; mt < 4; mt++) {
        #pragma unroll
        for (int q = 0; q < 2; q++) {
            const int r = m0 + warp_m * 64 + mt * 16 + fr + q * 8;
            const size_t go = (size_t)r * UNITS + ucol;
            const float2 cp = cellv[mt][q];
            const float pf0 = acc[mt][0][2*q],   pf1 = acc[mt][0][2*q+1];
            const float pi0 = acc[mt][1][2*q],   pi1 = acc[mt][1][2*q+1];
            const float pc0 = acc[mt][2][2*q],   pc1 = acc[mt][2][2*q+1];
            const float po0 = acc[mt][3][2*q],   po1 = acc[mt][3][2*q+1];

            float2 nh, nc;
            {
                const float f  = sig_(pf0 + Bf.x), ig = sig_(pi0 + Bi.x);
                const float cc = tanh_(pc0 + Bc.x), o = sig_(po0 + Bo.x);
                nc.x = f * cp.x + ig * cc; nh.x = o * tanh_(nc.x);
            }
            {
                const float f  = sig_(pf1 + Bf.y), ig = sig_(pi1 + Bi.y);
                const float cc = tanh_(pc1 + Bc.y), o = sig_(po1 + Bo.y);
                nc.y = f * cp.y + ig * cc; nh.y = o * tanh_(nc.y);
            }
            *(float2*)&out_h[go] = nh;
            *(float2*)&out_c[go] = nc;
        }
    }
}

// ---------------- host launch ----------------
extern "C" void kernel_launch(void* const* d_in, const int* in_sizes, int n_in,
                              void* d_out, int out_size) {
    const float* inp  = (const float*)d_in[0];
    const float* hid  = (const float*)d_in[1];
    const float* cell = (const float*)d_in[2];
    const float* Wf   = (const float*)d_in[3];
    const float* bf   = (const float*)d_in[4];
    const float* Wi   = (const float*)d_in[5];
    const float* bi   = (const float*)d_in[6];
    const float* Wc   = (const float*)d_in[7];
    const float* bc   = (const float*)d_in[8];
    const float* Wo   = (const float*)d_in[9];
    const float* bo   = (const float*)d_in[10];

    float* out_h = (float*)d_out;
    float* out_c = out_h + (size_t)BATCH * UNITS;

    cudaFuncSetAttribute(gemm_kernel,
                         cudaFuncAttributeMaxDynamicSharedMemorySize, SMEM_TOTAL);

    prep_kernel<<<8192, 256>>>(hid, inp, Wf, Wi, Wc, Wo);
    gemm_kernel<<<dim3(UNITS / BNU, BATCH / BM), 256, SMEM_TOTAL>>>(
        cell, bf, bi, bc, bo, out_h, out_c);
}

// round 17
// speedup vs baseline: 1.0217x; 1.0217x over previous
#include <cuda_runtime.h>
#include <cuda_fp16.h>
#include <cstdint>
#include <math.h>

// LSTM cell: fp16 mma.sync GEMM + register-direct fused gate epilogue.
// Round 17: exact round-15 kernel + pointer-increment loaders ONLY
// (round 16 isolated: cell-prefetch removed; epilogue loads cell as in r15).

#define BATCH 4096
#define UNITS 1024
#define KDIM  2048

#define BM 128
#define BNU 32              // units per CTA (x4 gates = 128 gemm cols)
#define BK 64
#define NSTAGE (KDIM / BK)  // 32
#define NBUF 3

#define ROW_B   144                     // 128B data + 16B pad (conflict-free)
#define TILE_B  (128 * ROW_B)           // 18432
#define OFF_AH  0
#define OFF_BH  TILE_B
#define STAGE_B (2 * TILE_B)            // 36864
#define MBAR_B  128
#define SMEM_TOTAL (MBAR_B + NBUF * STAGE_B)   // 110720 (x2 CTAs <= 228KB)

// ---------------- device scratch ----------------
__device__ __half g_Ah[(size_t)BATCH * KDIM];
__device__ __half g_Bh[(size_t)4 * UNITS * KDIM];   // row = gate*1024 + n, k contiguous

// ---------------- helpers ----------------
__device__ __forceinline__ uint32_t smem_u32(const void* p) {
    uint32_t a;
    asm("{ .reg .u64 t; cvta.to.shared.u64 t, %1; cvt.u32.u64 %0, t; }" : "=r"(a) : "l"(p));
    return a;
}
__device__ __forceinline__ void cp16(uint32_t dst, const void* src) {
    asm volatile("cp.async.cg.shared.global [%0], [%1], 16;" :: "r"(dst), "l"(src));
}
__device__ __forceinline__ void cpasync_arrive(uint32_t mbar) {
    asm volatile("cp.async.mbarrier.arrive.noinc.shared.b64 [%0];" :: "r"(mbar) : "memory");
}
__device__ __forceinline__ void mbar_init(uint32_t mbar, uint32_t cnt) {
    asm volatile("mbarrier.init.shared.b64 [%0], %1;" :: "r"(mbar), "r"(cnt) : "memory");
}
__device__ __forceinline__ void mbar_arrive(uint32_t mbar) {
    asm volatile("mbarrier.arrive.shared.b64 _, [%0];" :: "r"(mbar) : "memory");
}
__device__ __forceinline__ void mbar_wait(uint32_t mbar, uint32_t parity) {
    uint32_t done;
    asm volatile(
        "{\n\t.reg .pred p;\n\t"
        "mbarrier.try_wait.parity.acquire.cta.shared::cta.b64 p, [%1], %2;\n\t"
        "selp.b32 %0, 1, 0, p;\n\t}"
        : "=r"(done) : "r"(mbar), "r"(parity) : "memory");
    while (!done) {
        asm volatile(
            "{\n\t.reg .pred p;\n\t"
            "mbarrier.try_wait.parity.acquire.cta.shared::cta.b64 p, [%1], %2, 0x989680;\n\t"
            "selp.b32 %0, 1, 0, p;\n\t}"
            : "=r"(done) : "r"(mbar), "r"(parity) : "memory");
    }
}

#define LDSM4(r0, r1, r2, r3, addr) \
    asm volatile("ldmatrix.sync.aligned.m8n8.x4.shared.b16 {%0,%1,%2,%3}, [%4];" \
        : "=r"(r0), "=r"(r1), "=r"(r2), "=r"(r3) : "r"(addr))

__device__ __forceinline__ void mma_f16(float* c, const uint32_t* a, const uint32_t* b) {
    asm volatile(
        "mma.sync.aligned.m16n8k16.row.col.f32.f16.f16.f32 "
        "{%0,%1,%2,%3}, {%4,%5,%6,%7}, {%8,%9}, {%0,%1,%2,%3};"
        : "+f"(c[0]), "+f"(c[1]), "+f"(c[2]), "+f"(c[3])
        : "r"(a[0]), "r"(a[1]), "r"(a[2]), "r"(a[3]), "r"(b[0]), "r"(b[1]));
}

__device__ __forceinline__ float sig_(float x) {
    x = fminf(fmaxf(x, -30.f), 30.f);
    return __fdividef(1.f, 1.f + __expf(-x));
}
__device__ __forceinline__ float tanh_(float x) {
    x = fminf(fmaxf(x, -15.f), 15.f);
    float e = __expf(2.f * x);
    return __fdividef(e - 1.f, e + 1.f);
}

// ---------------- merged precompute ----------------
__global__ __launch_bounds__(256) void prep_kernel(
    const float* __restrict__ hid, const float* __restrict__ inp,
    const float* __restrict__ Wf, const float* __restrict__ Wi,
    const float* __restrict__ Wc, const float* __restrict__ Wo)
{
    __shared__ float tile[64][33];
    const int bid = blockIdx.x;
    if (bid < 4096) {
        const int row = bid;
        const int c8  = threadIdx.x * 8;   // 0..2040
        const float* src = (c8 < 1024) ? &hid[(size_t)row * 1024 + c8]
                                       : &inp[(size_t)row * 1024 + (c8 - 1024)];
        const float4 v0 = *(const float4*)src;
        const float4 v1 = *(const float4*)(src + 4);
        __half h[8];
        h[0] = __float2half_rn(v0.x); h[1] = __float2half_rn(v0.y);
        h[2] = __float2half_rn(v0.z); h[3] = __float2half_rn(v0.w);
        h[4] = __float2half_rn(v1.x); h[5] = __float2half_rn(v1.y);
        h[6] = __float2half_rn(v1.z); h[7] = __float2half_rn(v1.w);
        *(uint4*)&g_Ah[(size_t)row * KDIM + c8] = *(uint4*)h;
    } else {
        const int t  = bid - 4096;          // 4096 blocks: gate(4) x ktile(32) x ntile(32)
        const int g  = t >> 10;
        const int k0 = ((t >> 5) & 31) * 64;
        const int n0 = (t & 31) * 32;
        const float* W = (g == 0) ? Wf : (g == 1) ? Wi : (g == 2) ? Wc : Wo;
        const int lr = threadIdx.x >> 2;          // 0..63 (k row)
        const int lc = (threadIdx.x & 3) * 8;     // 0,8,16,24 (n col base)
        const float* src = &W[(size_t)(k0 + lr) * UNITS + n0 + lc];
        const float4 v0 = *(const float4*)src;
        const float4 v1 = *(const float4*)(src + 4);
        tile[lr][lc + 0] = v0.x; tile[lr][lc + 1] = v0.y;
        tile[lr][lc + 2] = v0.z; tile[lr][lc + 3] = v0.w;
        tile[lr][lc + 4] = v1.x; tile[lr][lc + 5] = v1.y;
        tile[lr][lc + 6] = v1.z; tile[lr][lc + 7] = v1.w;
        __syncthreads();
        const int n  = threadIdx.x >> 3;          // 0..31
        const int kq = (threadIdx.x & 7) * 8;     // 0..56
        __half h[8];
        #pragma unroll
        for (int j = 0; j < 8; j++)
            h[j] = __float2half_rn(tile[kq + j][n]);
        size_t o = ((size_t)g * UNITS + n0 + n) * KDIM + k0 + kq;
        *(uint4*)&g_Bh[o] = *(uint4*)h;
    }
}

// ---------------- fused GEMM + register epilogue ----------------
__global__ __launch_bounds__(256, 2) void gemm_kernel(
    const float* __restrict__ cell,
    const float* __restrict__ bfp, const float* __restrict__ bip,
    const float* __restrict__ bcp, const float* __restrict__ bop,
    float* __restrict__ out_h, float* __restrict__ out_c)
{
    extern __shared__ char smem[];
    const uint32_t sb = smem_u32(smem);
    const int tid  = threadIdx.x;
    const int wid  = tid >> 5;
    const int lane = tid & 31;
    const int warp_m = wid & 1;    // 64 rows
    const int warp_n = wid >> 1;   // 0..3 -> 8 units each, all 4 gates
    const int m0 = blockIdx.y * BM;
    const int n0 = blockIdx.x * BNU;

    if (tid == 0) {
        mbar_init(sb + 0,  256);
        mbar_init(sb + 8,  256);
        mbar_init(sb + 16, 256);
        mbar_init(sb + 24, 8);
        mbar_init(sb + 32, 8);
        mbar_init(sb + 40, 8);
    }
    __syncthreads();

    const uint32_t buf0 = sb + MBAR_B;

    // ---- pointer-increment loader state (stage offset is a constant multiple)
    const int row = tid >> 3;            // base row 0..31; rows row+32i
    const int c   = tid & 7;
    uint32_t s_a[4], s_b[4];
    const __half* g_a[4];
    const __half* g_b[4];
    #pragma unroll
    for (int i = 0; i < 4; i++) {
        const int r = row + i * 32;
        s_a[i] = OFF_AH + r * ROW_B + c * 16;
        s_b[i] = OFF_BH + r * ROW_B + c * 16;
        g_a[i] = &g_Ah[(size_t)(m0 + r) * KDIM + c * 8];
        const size_t gr = (size_t)(r >> 5) * UNITS + n0 + (r & 31);
        g_b[i] = &g_Bh[gr * KDIM + c * 8];
    }

    auto issue_stage = [&](int s, int b) {
        const uint32_t base = buf0 + b * STAGE_B;
        const int koff = s * BK;
        #pragma unroll
        for (int i = 0; i < 4; i++) {
            cp16(base + s_a[i], g_a[i] + koff);
            cp16(base + s_b[i], g_b[i] + koff);
        }
        cpasync_arrive(sb + b * 8);
    };

    const uint32_t a_off = (uint32_t)((warp_m * 64 + (lane & 15)) * ROW_B + (lane >> 4) * 16);
    const uint32_t b_off = (uint32_t)((((lane >> 4) & 1) * 32 + warp_n * 8 + (lane & 7)) * ROW_B
                                      + ((lane >> 3) & 1) * 16);

    float acc[4][4][4];   // [mt rows][gate][q]
    #pragma unroll
    for (int i = 0; i < 4; i++)
        #pragma unroll
        for (int j = 0; j < 4; j++)
            #pragma unroll
            for (int q = 0; q < 4; q++) acc[i][j][q] = 0.f;

    auto stage_body = [&](int s, int b, int prodPar, int consPar,
                          bool produce, bool freewait) {
        const int b2 = (b + 2) % 3;
        if (produce) {
            if (freewait) mbar_wait(sb + 24 + b2 * 8, prodPar);
            issue_stage(s + 2, b2);
        }
        mbar_wait(sb + b * 8, consPar);

        const uint32_t base = buf0 + b * STAGE_B;
        #pragma unroll
        for (int ksub = 0; ksub < 4; ksub++) {
            const uint32_t kb = ksub * 32;
            uint32_t aH[4][4], bH[4][2];
            #pragma unroll
            for (int mt = 0; mt < 4; mt++) {
                const uint32_t ra = base + a_off + mt * 16 * ROW_B + kb;
                LDSM4(aH[mt][0], aH[mt][1], aH[mt][2], aH[mt][3], ra + OFF_AH);
            }
            #pragma unroll
            for (int p = 0; p < 2; p++) {
                const uint32_t rb = base + b_off + p * 64 * ROW_B + kb;
                LDSM4(bH[2*p][0], bH[2*p][1], bH[2*p+1][0], bH[2*p+1][1], rb + OFF_BH);
            }
            if (ksub == 3) {
                if (lane == 0) mbar_arrive(sb + 24 + b * 8);   // release early
            }
            #pragma unroll
            for (int mt = 0; mt < 4; mt++)
                #pragma unroll
                for (int g = 0; g < 4; g++)
                    mma_f16(acc[mt][g], aH[mt], bH[g]);
        }
    };

    issue_stage(0, 0);
    issue_stage(1, 1);

    // NSTAGE = 32 = 10*3 + 2; unrolled by NBUF so buffer indices are constants.
    #pragma unroll 1
    for (int i = 0; i < 10; i++) {
        const int s = i * 3;
        const int p = i & 1;
        stage_body(s,     0, p ^ 1, p, true, i >= 1);
        stage_body(s + 1, 1, p,     p, true, true);
        stage_body(s + 2, 2, p,     p, true, true);
    }
    stage_body(30, 0, 0, 0, false, false);
    stage_body(31, 1, 0, 0, false, false);

    // ---- register-direct epilogue (cell loaded here, as in round 15)
    const int fr = lane >> 2;
    const int fc = (lane & 3) * 2;
    const int ucol = n0 + warp_n * 8 + fc;
    const float2 Bf = *(const float2*)&bfp[ucol];
    const float2 Bi = *(const float2*)&bip[ucol];
    const float2 Bc = *(const float2*)&bcp[ucol];
    const float2 Bo = *(const float2*)&bop[ucol];

    #pragma unroll
    for (int mt = 0; mt < 4; mt++) {
        #pragma unroll
        for (int q = 0; q < 2; q++) {
            const int r = m0 + warp_m * 64 + mt * 16 + fr + q * 8;
            const size_t go = (size_t)r * UNITS + ucol;
            const float2 cp = *(const float2*)&cell[go];
            const float pf0 = acc[mt][0][2*q],   pf1 = acc[mt][0][2*q+1];
            const float pi0 = acc[mt][1][2*q],   pi1 = acc[mt][1][2*q+1];
            const float pc0 = acc[mt][2][2*q],   pc1 = acc[mt][2][2*q+1];
            const float po0 = acc[mt][3][2*q],   po1 = acc[mt][3][2*q+1];

            float2 nh, nc;
            {
                const float f  = sig_(pf0 + Bf.x), ig = sig_(pi0 + Bi.x);
                const float cc = tanh_(pc0 + Bc.x), o = sig_(po0 + Bo.x);
                nc.x = f * cp.x + ig * cc; nh.x = o * tanh_(nc.x);
            }
            {
                const float f  = sig_(pf1 + Bf.y), ig = sig_(pi1 + Bi.y);
                const float cc = tanh_(pc1 + Bc.y), o = sig_(po1 + Bo.y);
                nc.y = f * cp.y + ig * cc; nh.y = o * tanh_(nc.y);
            }
            *(float2*)&out_h[go] = nh;
            *(float2*)&out_c[go] = nc;
        }
    }
}

// ---------------- host launch ----------------
extern "C" void kernel_launch(void* const* d_in, const int* in_sizes, int n_in,
                              void* d_out, int out_size) {
    const float* inp  = (const float*)d_in[0];
    const float* hid  = (const float*)d_in[1];
    const float* cell = (const float*)d_in[2];
    const float* Wf   = (const float*)d_in[3];
    const float* bf   = (const float*)d_in[4];
    const float* Wi   = (const float*)d_in[5];
    const float* bi   = (const float*)d_in[6];
    const float* Wc   = (const float*)d_in[7];
    const float* bc   = (const float*)d_in[8];
    const float* Wo   = (const float*)d_in[9];
    const float* bo   = (const float*)d_in[10];

    float* out_h = (float*)d_out;
    float* out_c = out_h + (size_t)BATCH * UNITS;

    cudaFuncSetAttribute(gemm_kernel,
                         cudaFuncAttributeMaxDynamicSharedMemorySize, SMEM_TOTAL);

    prep_kernel<<<8192, 256>>>(hid, inp, Wf, Wi, Wc, Wo);
    gemm_kernel<<<dim3(UNITS / BNU, BATCH / BM), 256, SMEM_TOTAL>>>(
        cell, bf, bi, bc, bo, out_h, out_c);
}